// round 16
// baseline (speedup 1.0000x reference)
#include <cuda_runtime.h>
#include <cstdint>

// ---------------------------------------------------------------------------
// RSSMCore: T=64 sequential steps, B=256.  PASSING MODEL (locked since R6):
//  * RNG: jax_threefry_partitionable: bits(i) = o0^o1 of threefry(key,(0,i)).
//  * GEMM: exact f32, per-output ascending-k single-accumulator FMA chain
//    (BK=16 tiles ascending) — flip-free at rel_err 9.051719e-07.
//    Per-output arithmetic MUST NOT change (thread mapping may).
//  * z weights w = fl(1+p)-p carried into the W_in gather.
//  * XLA rational tanh / logistic / cephes exp/log, FMA-form.
// Round 16 (perf only). R15 profile: fma=40.6%, L1=71.1% -> smem crossbar
// bound at 1.5 B/FMA. Fix: TM=8 x TN=8 register tile on 128-thread blocks
// (same 64x128 block tiles, same grid widths) -> 1.0 B/FMA, FMA-bound.
// All pipeline roles rebuilt for 128-thread blocks; 1216-block 1D grid in
// dependency order (monotone dispatch -> deadlock-free).
// ---------------------------------------------------------------------------

#define T_STEPS 64
#define B 256
#define GRU_H 2048
#define MLP 1000
#define ZF 1024
#define FDIM 1024
#define G3 (3 * GRU_H)   // 6144

// ---------------- scratch (device globals; no allocation allowed) ----------
__device__ float g_x[B * MLP];
__device__ float g_gi[B * G3];
__device__ float g_gh[B * G3];
__device__ float g_h[B * GRU_H];
__device__ float g_p1[B * MLP];
__device__ float g_q1[B * MLP];
__device__ int   g_cnt[T_STEPS][5];   // 0:gru 1:q1 2:p1 3:post 4:x

// =================== XLA-matched elementwise math (FMA form) ================

__device__ __forceinline__ float xla_tanh(float x) {
    if (fabsf(x) < 0.0004f) return x;
    float xc = fminf(fmaxf(x, -7.90531110763549805f), 7.90531110763549805f);
    float x2 = __fmul_rn(xc, xc);
    float p = -2.76076847742355e-16f;
    p = __fmaf_rn(p, x2, 2.00018790482477e-13f);
    p = __fmaf_rn(p, x2, -8.60467152213735e-11f);
    p = __fmaf_rn(p, x2, 5.12229709037114e-08f);
    p = __fmaf_rn(p, x2, 1.48572235717979e-05f);
    p = __fmaf_rn(p, x2, 6.37261928875436e-04f);
    p = __fmaf_rn(p, x2, 4.89352455891786e-03f);
    p = __fmul_rn(p, xc);
    float q = 1.19825839466702e-06f;
    q = __fmaf_rn(q, x2, 1.18534705686654e-04f);
    q = __fmaf_rn(q, x2, 2.26843463243900e-03f);
    q = __fmaf_rn(q, x2, 4.89352518554385e-03f);
    return __fdiv_rn(p, q);
}

__device__ __forceinline__ float xla_sigmoid(float x) {
    return __fmaf_rn(0.5f, xla_tanh(__fmul_rn(0.5f, x)), 0.5f);
}

__device__ __forceinline__ float xla_log(float a) {
    int ix = __float_as_int(a);
    float e = (float)((ix >> 23) - 126);
    float m = __int_as_float((ix & 0x007fffff) | 0x3f000000);
    if (m < 0.707106781186547524f) { e = __fadd_rn(e, -1.0f); m = __fadd_rn(m, m); }
    m = __fadd_rn(m, -1.0f);
    float z = __fmul_rn(m, m);
    float y = 7.0376836292e-2f;
    y = __fmaf_rn(y, m, -1.1514610310e-1f);
    y = __fmaf_rn(y, m, 1.1676998740e-1f);
    y = __fmaf_rn(y, m, -1.2420140846e-1f);
    y = __fmaf_rn(y, m, 1.4249322787e-1f);
    y = __fmaf_rn(y, m, -1.6668057665e-1f);
    y = __fmaf_rn(y, m, 2.0000714765e-1f);
    y = __fmaf_rn(y, m, -2.4999993993e-1f);
    y = __fmaf_rn(y, m, 3.3333331174e-1f);
    y = __fmul_rn(__fmul_rn(y, m), z);
    y = __fmaf_rn(e, -2.12194440e-4f, y);
    y = __fmaf_rn(z, -0.5f, y);
    float r = __fadd_rn(m, y);
    r = __fmaf_rn(e, 0.693359375f, r);
    return r;
}

__device__ __forceinline__ float xla_exp(float x) {
    float xc = fminf(fmaxf(x, -87.33654f), 88.72283f);
    float m = floorf(__fmaf_rn(xc, 1.44269504088896341f, 0.5f));
    float r = __fmaf_rn(m, -0.693359375f, xc);
    r = __fmaf_rn(m, 2.12194440e-4f, r);
    float r2 = __fmul_rn(r, r);
    float p = 1.9875691500e-4f;
    p = __fmaf_rn(p, r, 1.3981999507e-3f);
    p = __fmaf_rn(p, r, 8.3334519073e-3f);
    p = __fmaf_rn(p, r, 4.1665795894e-2f);
    p = __fmaf_rn(p, r, 1.6666665459e-1f);
    p = __fmaf_rn(p, r, 5.0000001201e-1f);
    float y = __fadd_rn(__fmaf_rn(p, r2, r), 1.0f);
    return __fmul_rn(y, __int_as_float(((int)m + 127) << 23));
}

__device__ __forceinline__ float xla_expm1(float x) {
    if (fabsf(x) < 1e-5f) return __fmaf_rn(__fmul_rn(0.5f, x), x, x);
    return __fadd_rn(xla_exp(x), -1.0f);
}

__device__ __forceinline__ float xla_elu(float x) {
    return (x > 0.0f) ? x : xla_expm1(x);
}

// ---------------- threefry2x32 (JAX bit-exact) ------------------------------
__device__ __forceinline__ uint32_t rotl32(uint32_t v, int r) {
    return (v << r) | (v >> (32 - r));
}

__device__ __forceinline__ void threefry2x32(uint32_t k0, uint32_t k1,
                                             uint32_t x0, uint32_t x1,
                                             uint32_t& o0, uint32_t& o1) {
    uint32_t ks2 = k0 ^ k1 ^ 0x1BD11BDAu;
    x0 += k0; x1 += k1;
    x0 += x1; x1 = rotl32(x1, 13); x1 ^= x0;
    x0 += x1; x1 = rotl32(x1, 15); x1 ^= x0;
    x0 += x1; x1 = rotl32(x1, 26); x1 ^= x0;
    x0 += x1; x1 = rotl32(x1,  6); x1 ^= x0;
    x0 += k1; x1 += ks2 + 1u;
    x0 += x1; x1 = rotl32(x1, 17); x1 ^= x0;
    x0 += x1; x1 = rotl32(x1, 29); x1 ^= x0;
    x0 += x1; x1 = rotl32(x1, 16); x1 ^= x0;
    x0 += x1; x1 = rotl32(x1, 24); x1 ^= x0;
    x0 += ks2; x1 += k0 + 2u;
    x0 += x1; x1 = rotl32(x1, 13); x1 ^= x0;
    x0 += x1; x1 = rotl32(x1, 15); x1 ^= x0;
    x0 += x1; x1 = rotl32(x1, 26); x1 ^= x0;
    x0 += x1; x1 = rotl32(x1,  6); x1 ^= x0;
    x0 += k0; x1 += k1 + 3u;
    x0 += x1; x1 = rotl32(x1, 17); x1 ^= x0;
    x0 += x1; x1 = rotl32(x1, 29); x1 ^= x0;
    x0 += x1; x1 = rotl32(x1, 16); x1 ^= x0;
    x0 += x1; x1 = rotl32(x1, 24); x1 ^= x0;
    x0 += k1; x1 += ks2 + 4u;
    x0 += x1; x1 = rotl32(x1, 13); x1 ^= x0;
    x0 += x1; x1 = rotl32(x1, 15); x1 ^= x0;
    x0 += x1; x1 = rotl32(x1, 26); x1 ^= x0;
    x0 += x1; x1 = rotl32(x1,  6); x1 ^= x0;
    x0 += ks2; x1 += k0 + 5u;
    o0 = x0; o1 = x1;
}

__device__ __forceinline__ uint32_t jax_bits32(uint32_t k0, uint32_t k1, uint32_t i) {
    uint32_t o0, o1;
    threefry2x32(k0, k1, 0u, i, o0, o1);
    return o0 ^ o1;
}

// ---------------- counter sync helpers --------------------------------------
__device__ __forceinline__ void role_signal(int t, int slot) {
    __threadfence();
    __syncthreads();
    if (threadIdx.x == 0) atomicAdd(&g_cnt[t][slot], 1);
}

__device__ __forceinline__ void role_wait(int t, int slot, int target) {
    if (threadIdx.x == 0) {
        while (atomicAdd(&g_cnt[t][slot], 0) < target) __nanosleep(64);
        __threadfence();
    }
    __syncthreads();
}

// ---------------- guarded float4 load ---------------------------------------
__device__ __forceinline__ float4 load_f4_guard(const float* __restrict__ src,
                                                size_t base, int k, int Klim) {
    if (k + 3 < Klim) return *reinterpret_cast<const float4*>(&src[base]);
    float4 v;
    v.x = (k + 0 < Klim) ? src[base + 0] : 0.f;
    v.y = (k + 1 < Klim) ? src[base + 1] : 0.f;
    v.z = (k + 2 < Klim) ? src[base + 2] : 0.f;
    v.w = (k + 3 < Klim) ? src[base + 3] : 0.f;
    return v;
}

// ---------------- templated GEMM core: 128 threads, double-buffered ----------
// BM x BN block tile, TM x TN register tile, 128 threads = (BM/TM)*(BN/TN).
// tx = tid&15 (col groups of 4, split +64 when TN==8), ty = tid>>4 (0..7).
// Per-output arithmetic: locked ascending-k single-accumulator FMA chain
// over BK=16 tiles — identical chain per (row,col) to R13.
#define SMEM_BYTES 25088   // sizeof largest variant (64x128)

template<int BM, int BN, int TM, int TN>
__device__ void gemm_core_t(char* smraw,
    const float* __restrict__ A, const float* __restrict__ W,
    const float* __restrict__ bias, float* __restrict__ C,
    int K, int N, bool act, bool fuse,
    const float* __restrict__ feat, int concatK, int bm, int bn)
{
    struct Sm { float As[2][16][BM + 4]; float Ws[2][16][BN]; };
    Sm* sm = reinterpret_cast<Sm*>(smraw);
    constexpr int NA = BM / 32;          // A float4 stage loads per thread
    constexpr int NWL = BN / 32;         // W float4 stage loads per thread
    constexpr int WROWF4 = BN / 4;       // float4s per W row
    const int lda = fuse ? concatK : K;
    const int tid = threadIdx.x;         // 0..127
    const int tx = tid & 15;
    const int ty = tid >> 4;             // 0..7

    float acc[TM][TN];
#pragma unroll
    for (int i = 0; i < TM; i++)
#pragma unroll
        for (int j = 0; j < TN; j++) acc[i][j] = 0.f;

    const int ntiles = (K + 15) >> 4;

    float4 aR[NA], wR[NWL];
    auto load_tile = [&](int k0) {
#pragma unroll
        for (int l = 0; l < NA; l++) {
            int e = tid + l * 128;
            int arow = e >> 2, ac4 = e & 3;
            int ka = k0 + ac4 * 4;
            if (fuse && ka >= concatK)
                aR[l] = load_f4_guard(feat, (size_t)(bm + arow) * FDIM + (ka - concatK), ka, K);
            else
                aR[l] = load_f4_guard(A, (size_t)(bm + arow) * lda + ka, ka, K);
        }
#pragma unroll
        for (int l = 0; l < NWL; l++) {
            int e = tid + l * 128;
            int wrow = e / WROWF4, wcol4 = e % WROWF4;
            int kw = k0 + wrow;
            int col = bn + wcol4 * 4;
            if (kw < K) {
                if (col + 3 < N) wR[l] = *reinterpret_cast<const float4*>(&W[(size_t)kw * N + col]);
                else wR[l] = load_f4_guard(W, (size_t)kw * N + col, col, N);
            } else wR[l] = make_float4(0.f, 0.f, 0.f, 0.f);
        }
    };
    auto store_tile = [&](int buf) {
#pragma unroll
        for (int l = 0; l < NA; l++) {
            int e = tid + l * 128;
            int arow = e >> 2, ac4 = e & 3;
            sm->As[buf][ac4 * 4 + 0][arow] = aR[l].x;
            sm->As[buf][ac4 * 4 + 1][arow] = aR[l].y;
            sm->As[buf][ac4 * 4 + 2][arow] = aR[l].z;
            sm->As[buf][ac4 * 4 + 3][arow] = aR[l].w;
        }
#pragma unroll
        for (int l = 0; l < NWL; l++) {
            int e = tid + l * 128;
            int wrow = e / WROWF4, wcol4 = e % WROWF4;
            *reinterpret_cast<float4*>(&sm->Ws[buf][wrow][wcol4 * 4]) = wR[l];
        }
    };

    load_tile(0);
    store_tile(0);
    __syncthreads();

    int buf = 0;
    for (int tI = 0; tI < ntiles; tI++) {
        const bool more = (tI + 1 < ntiles);
        if (more) load_tile((tI + 1) << 4);

#pragma unroll
        for (int kk = 0; kk < 16; kk++) {
            float a_[TM];
#pragma unroll
            for (int q = 0; q < TM / 4; q++) {
                float4 av = *reinterpret_cast<const float4*>(&sm->As[buf][kk][ty * TM + q * 4]);
                a_[q * 4 + 0] = av.x; a_[q * 4 + 1] = av.y;
                a_[q * 4 + 2] = av.z; a_[q * 4 + 3] = av.w;
            }
            float w_[TN];
#pragma unroll
            for (int h = 0; h < TN / 4; h++) {
                float4 wv = *reinterpret_cast<const float4*>(&sm->Ws[buf][kk][h * 64 + tx * 4]);
                w_[h * 4 + 0] = wv.x; w_[h * 4 + 1] = wv.y;
                w_[h * 4 + 2] = wv.z; w_[h * 4 + 3] = wv.w;
            }
#pragma unroll
            for (int i = 0; i < TM; i++)
#pragma unroll
                for (int j = 0; j < TN; j++)
                    acc[i][j] = __fmaf_rn(a_[i], w_[j], acc[i][j]);
        }
        if (more) {
            store_tile(buf ^ 1);
            __syncthreads();
            buf ^= 1;
        }
    }

    const bool fullN = (bn + BN <= N);
#pragma unroll
    for (int i = 0; i < TM; i++) {
        int row = bm + ty * TM + i;
#pragma unroll
        for (int h = 0; h < TN / 4; h++) {
            int colb = bn + h * 64 + tx * 4;
            float v[4];
#pragma unroll
            for (int j = 0; j < 4; j++) {
                float x = acc[i][h * 4 + j];
                int col = colb + j;
                if (col < N) {
                    if (bias) x = __fadd_rn(x, bias[col]);
                    if (act) x = xla_elu(x);
                }
                v[j] = x;
            }
            if (fullN) {
                *reinterpret_cast<float4*>(&C[(size_t)row * N + colb]) =
                    make_float4(v[0], v[1], v[2], v[3]);
            } else {
#pragma unroll
                for (int j = 0; j < 4; j++)
                    if (colb + j < N) C[(size_t)row * N + colb + j] = v[j];
            }
        }
    }
}

// ---------------- gru element (identical arithmetic to R11..R15) -------------
__device__ __forceinline__ void gru_elem(int i4) {
    int b = i4 >> 9;
    int j4 = i4 & 511;
    const float4* gib = reinterpret_cast<const float4*>(g_gi + (size_t)b * G3);
    const float4* ghb = reinterpret_cast<const float4*>(g_gh + (size_t)b * G3);
    float4 ir4 = gib[j4],        hr4 = ghb[j4];
    float4 iz4 = gib[512 + j4],  hz4 = ghb[512 + j4];
    float4 in4 = gib[1024 + j4], hn4 = ghb[1024 + j4];
    float4 hp4 = reinterpret_cast<const float4*>(g_h)[i4];
    float4 o;
    {
        float r  = xla_sigmoid(__fadd_rn(ir4.x, hr4.x));
        float zg = xla_sigmoid(__fadd_rn(iz4.x, hz4.x));
        float n  = xla_tanh(__fmaf_rn(r, hn4.x, in4.x));
        o.x = __fmaf_rn(zg, hp4.x, __fmul_rn(__fsub_rn(1.0f, zg), n));
    }
    {
        float r  = xla_sigmoid(__fadd_rn(ir4.y, hr4.y));
        float zg = xla_sigmoid(__fadd_rn(iz4.y, hz4.y));
        float n  = xla_tanh(__fmaf_rn(r, hn4.y, in4.y));
        o.y = __fmaf_rn(zg, hp4.y, __fmul_rn(__fsub_rn(1.0f, zg), n));
    }
    {
        float r  = xla_sigmoid(__fadd_rn(ir4.z, hr4.z));
        float zg = xla_sigmoid(__fadd_rn(iz4.z, hz4.z));
        float n  = xla_tanh(__fmaf_rn(r, hn4.z, in4.z));
        o.z = __fmaf_rn(zg, hp4.z, __fmul_rn(__fsub_rn(1.0f, zg), n));
    }
    {
        float r  = xla_sigmoid(__fadd_rn(ir4.w, hr4.w));
        float zg = xla_sigmoid(__fadd_rn(iz4.w, hz4.w));
        float n  = xla_tanh(__fmaf_rn(r, hn4.w, in4.w));
        o.w = __fmaf_rn(zg, hp4.w, __fmul_rn(__fsub_rn(1.0f, zg), n));
    }
    reinterpret_cast<float4*>(g_h)[i4] = o;
}

// ---------------- per-step pipelined mega-kernel (128 threads/block) ---------
// 1D grid, 1216 blocks, range-decoded roles in dependency order:
//  [0,256)     gru (grid-stride)          -> signal 0
//  [256,384)   q1  32x64  (wait 0=256)    -> signal 1
//  [384,576)   gh  64x128 (wait 0=256)    [skip at last]
//  [576,608)   p1  64x128 (wait 0=256)    -> signal 2
//  [608,736)   post 32x64 (wait 1=128)    -> signal 3
//  [736,768)   prior 64x128 (wait 2=32)
//  [768,1024)  sample+x (wait 3=128)      -> signal 4   [skip at last]
//  [1024,1216) gi  64x128 (wait 4=256)    [skip at last]
__global__ __launch_bounds__(128) void step_kernel(
    const float* __restrict__ W_ih, const float* __restrict__ W_hh,
    const float* __restrict__ Wp1,  const float* __restrict__ Wq1,
    const float* __restrict__ Wp2,  const float* __restrict__ Wq2,
    const float* __restrict__ b_ih, const float* __restrict__ b_hh,
    const float* __restrict__ bp1,  const float* __restrict__ bq1,
    const float* __restrict__ bp2,  const float* __restrict__ bq2,
    const float* __restrict__ W_in, const float* __restrict__ b_in,
    const int* __restrict__ actions,
    const float* __restrict__ feat,
    float* __restrict__ out_prior, float* __restrict__ out_post,
    int t, int last)
{
    __shared__ __align__(16) char smraw[SMEM_BYTES];
    const int gb = blockIdx.x;              // 0..1215

    if (gb < 256) {           // gru: h_t = gru(gi_t, gh_t, h_{t-1})
        const int total = B * GRU_H / 4;    // 131072 float4 units
        for (int i4 = gb * 128 + threadIdx.x; i4 < total; i4 += 256 * 128)
            gru_elem(i4);
        role_signal(t, 0);
    } else if (gb < 384) {    // q1 = elu([h|feat] @ Wq1 + bq1)  K=3072, N=1000
        int r = gb - 256;
        role_wait(t, 0, 256);
        int bm = (r & 7) * 32, bn = (r >> 3) * 64;
        gemm_core_t<32, 64, 4, 4>(smraw, g_h, Wq1, bq1, g_q1, GRU_H + FDIM, MLP,
                                  true, true, feat, GRU_H, bm, bn);
        role_signal(t, 1);
    } else if (gb < 576) {    // gh_{t+1} = h @ W_hh + b_hh      K=2048, N=6144
        if (last) return;
        int r = gb - 384;
        role_wait(t, 0, 256);
        gemm_core_t<64, 128, 8, 8>(smraw, g_h, W_hh, b_hh, g_gh, GRU_H, G3,
                                   false, false, nullptr, 0, (r & 3) * 64, (r >> 2) * 128);
    } else if (gb < 608) {    // p1 = elu(h @ Wp1 + bp1)         K=2048, N=1000
        int r = gb - 576;
        role_wait(t, 0, 256);
        gemm_core_t<64, 128, 8, 8>(smraw, g_h, Wp1, bp1, g_p1, GRU_H, MLP,
                                   true, false, nullptr, 0, (r & 3) * 64, (r >> 2) * 128);
        role_signal(t, 2);
    } else if (gb < 736) {    // post = q1 @ Wq2 + bq2           K=1000, N=1024
        int r = gb - 608;
        role_wait(t, 1, 128);
        int bm = (r & 7) * 32, bn = (r >> 3) * 64;
        gemm_core_t<32, 64, 4, 4>(smraw, g_q1, Wq2, bq2, out_post, MLP, ZF,
                                  false, false, nullptr, 0, bm, bn);
        role_signal(t, 3);
    } else if (gb < 768) {    // prior = p1 @ Wp2 + bp2          K=1000, N=1024
        int r = gb - 736;
        role_wait(t, 2, 32);
        gemm_core_t<64, 128, 8, 8>(smraw, g_p1, Wp2, bp2, out_prior, MLP, ZF,
                                   false, false, nullptr, 0, (r & 3) * 64, (r >> 2) * 128);
    } else if (gb < 1024) {   // sample z_t + x_{t+1}  (1 batch per block)
        if (last) return;
        int b = gb - 768;                   // 0..255
        role_wait(t, 3, 128);

        __shared__ int   idx[32];
        __shared__ float wgt[32];

        int warp = threadIdx.x >> 5;        // 0..3
        int lane = threadIdx.x & 31;

        uint32_t k0, k1;
        threefry2x32(0u, 42u, 0u, (uint32_t)t, k0, k1);
        const float TINY = 1.1754943508222875e-38f;

        for (int c = warp; c < 32; c += 4) {
            float l = out_post[(size_t)b * ZF + c * 32 + lane];
            uint32_t i = (uint32_t)((b * 32 + c) * 32 + lane);
            uint32_t bits = jax_bits32(k0, k1, i);
            float f = __fadd_rn(__uint_as_float((bits >> 9) | 0x3f800000u), -1.0f);
            float u = fmaxf(TINY, __fadd_rn(f, TINY));
            float g = -xla_log(-xla_log(u));
            float v = __fadd_rn(l, g);

            float bv = v; int bi = lane;
#pragma unroll
            for (int off = 16; off > 0; off >>= 1) {
                float ov = __shfl_down_sync(0xffffffffu, bv, off);
                int   oi = __shfl_down_sync(0xffffffffu, bi, off);
                if (ov > bv || (ov == bv && oi < bi)) { bv = ov; bi = oi; }
            }
            bi = __shfl_sync(0xffffffffu, bi, 0);

            float m = l;
#pragma unroll
            for (int off = 16; off > 0; off >>= 1)
                m = fmaxf(m, __shfl_xor_sync(0xffffffffu, m, off));
            float e = xla_exp(__fadd_rn(l, -m));
            float s = 0.f;
#pragma unroll
            for (int ll = 0; ll < 32; ll++)
                s = __fadd_rn(s, __shfl_sync(0xffffffffu, e, ll));
            float p = __fdiv_rn(e, s);
            float psel = __shfl_sync(0xffffffffu, p, bi);
            if (lane == 0) {
                idx[c] = bi;
                wgt[c] = __fadd_rn(__fadd_rn(1.0f, psel), -psel);  // fl(1+p)-p
            }
        }
        __syncthreads();

        int a = actions[t * B + b];         // act_seq[t+1] = actions[t]
        for (int j = threadIdx.x; j < MLP; j += 128) {
            float s = 0.f;
#pragma unroll
            for (int c = 0; c < 32; c++)
                s = __fmaf_rn(wgt[c], W_in[(size_t)(c * 32 + idx[c]) * MLP + j], s);
            s = __fmaf_rn(1.0f, W_in[(size_t)(ZF + a) * MLP + j], s);
            s = __fadd_rn(s, b_in[j]);
            g_x[b * MLP + j] = xla_elu(s);
        }
        role_signal(t, 4);
    } else {                  // gi_{t+1} = x @ W_ih + b_ih      K=1000, N=6144
        if (last) return;
        int r = gb - 1024;
        role_wait(t, 4, 256);
        gemm_core_t<64, 128, 8, 8>(smraw, g_x, W_ih, b_ih, g_gi, MLP, G3,
                                   false, false, nullptr, 0, (r & 3) * 64, (r >> 2) * 128);
    }
}

// ---------------- prologue kernels -------------------------------------------
__global__ __launch_bounds__(256) void reset_kernel()
{
    int i = blockIdx.x * blockDim.x + threadIdx.x;
    if (i < T_STEPS * 5) (&g_cnt[0][0])[i] = 0;
    for (int j = i; j < B * GRU_H; j += gridDim.x * blockDim.x) g_h[j] = 0.f;
}

__global__ __launch_bounds__(256) void compute_x0_kernel(
    const float* __restrict__ W_in, const float* __restrict__ b_in)
{
    int b = blockIdx.x;
    for (int j = threadIdx.x; j < MLP; j += blockDim.x) {
        float s = W_in[(size_t)ZF * MLP + j];   // action 0 row, weight 1
        s = __fadd_rn(s, b_in[j]);
        g_x[b * MLP + j] = xla_elu(s);
    }
}

// prologue dual GEMM: gi_0 | gh_0 (z selects), grid (4, 48, 2), 128 threads
__global__ __launch_bounds__(128) void gemm0_kernel(
    const float* __restrict__ W_ih, const float* __restrict__ W_hh,
    const float* __restrict__ b_ih, const float* __restrict__ b_hh)
{
    __shared__ __align__(16) char smraw[SMEM_BYTES];
    const int bm = blockIdx.x * 64;
    const int bn = blockIdx.y * 128;
    if (blockIdx.z == 0)
        gemm_core_t<64, 128, 8, 8>(smraw, g_x, W_ih, b_ih, g_gi, MLP, G3,
                                   false, false, nullptr, 0, bm, bn);
    else
        gemm_core_t<64, 128, 8, 8>(smraw, g_h, W_hh, b_hh, g_gh, GRU_H, G3,
                                   false, false, nullptr, 0, bm, bn);
}

// ---------------------------------------------------------------------------
extern "C" void kernel_launch(void* const* d_in, const int* in_sizes, int n_in,
                              void* d_out, int out_size)
{
    const float* features = (const float*)d_in[0];   // [64,256,1024]
    const int*   actions  = (const int*)  d_in[1];   // [64,256]
    const float* W_in = (const float*)d_in[2];
    const float* b_in = (const float*)d_in[3];
    const float* W_ih = (const float*)d_in[4];
    const float* W_hh = (const float*)d_in[5];
    const float* b_ih = (const float*)d_in[6];
    const float* b_hh = (const float*)d_in[7];
    const float* Wp1  = (const float*)d_in[8];
    const float* bp1  = (const float*)d_in[9];
    const float* Wp2  = (const float*)d_in[10];
    const float* bp2  = (const float*)d_in[11];
    const float* Wq1  = (const float*)d_in[12];
    const float* bq1  = (const float*)d_in[13];
    const float* Wq2  = (const float*)d_in[14];
    const float* bq2  = (const float*)d_in[15];
    float* out = (float*)d_out;                      // [2,64,256,32,32]

    reset_kernel<<<(B * GRU_H + 255) / 256, 256>>>();
    compute_x0_kernel<<<B, 256>>>(W_in, b_in);
    gemm0_kernel<<<dim3(4, 48, 2), 128>>>(W_ih, W_hh, b_ih, b_hh);

    for (int t = 0; t < T_STEPS; t++) {
        const float* feat_t = features + (size_t)t * B * FDIM;
        float* out_prior = out + (size_t)t * B * ZF;
        float* out_post  = out + ((size_t)(T_STEPS + t)) * B * ZF;

        step_kernel<<<1216, 128>>>(
            W_ih, W_hh, Wp1, Wq1, Wp2, Wq2,
            b_ih, b_hh, bp1, bq1, bp2, bq2,
            W_in, b_in, actions, feat_t, out_prior, out_post,
            t, (t == T_STEPS - 1) ? 1 : 0);
    }
}